// round 1
// baseline (speedup 1.0000x reference)
#include <cuda_runtime.h>
#include <math.h>

// Problem dims (fixed by reference)
#define BB 8
#define LL 2048
#define DIN 512
#define HH 1024
#define NS 16
#define RR 64
#define MM (BB * LL)   // 16384

// ---------------- scratch (device globals; no allocation allowed) ----------
__device__ float g_xn [(size_t)MM * DIN];   // layernorm output
__device__ float g_h  [(size_t)MM * HH];    // in_proj output
__device__ float g_hc [(size_t)MM * HH];    // conv+silu output
__device__ float g_dtr[(size_t)MM * RR];    // dt hidden
__device__ float g_dt [(size_t)MM * HH];    // dt (softplus)
__device__ float g_y  [(size_t)MM * HH];    // scan output

// ---------------- helpers ---------------------------------------------------
__device__ __forceinline__ float blockReduce128(float v, float* sh) {
    // 128 threads = 4 warps
    #pragma unroll
    for (int o = 16; o > 0; o >>= 1) v += __shfl_xor_sync(0xffffffffu, v, o);
    int w = threadIdx.x >> 5;
    if ((threadIdx.x & 31) == 0) sh[w] = v;
    __syncthreads();
    float r = sh[0] + sh[1] + sh[2] + sh[3];
    __syncthreads();
    return r;
}

__device__ __forceinline__ float softplusf(float v) {
    return (v > 20.f) ? v : log1pf(expf(v));
}

// ---------------- LayerNorm: one block (128 thr) per row of 512 -------------
__global__ void ln_kernel(const float* __restrict__ x,
                          const float* __restrict__ gamma,
                          const float* __restrict__ beta,
                          float* __restrict__ out) {
    __shared__ float sh[4];
    size_t row = blockIdx.x;
    const float4* xr = (const float4*)(x + row * DIN);
    float4 v = xr[threadIdx.x];
    float s = blockReduce128(v.x + v.y + v.z + v.w, sh);
    float mu = s * (1.f / DIN);
    float dx = v.x - mu, dy = v.y - mu, dz = v.z - mu, dw = v.w - mu;
    float s2 = blockReduce128(dx*dx + dy*dy + dz*dz + dw*dw, sh);
    float rstd = rsqrtf(s2 * (1.f / DIN) + 1e-5f);
    float4 gv = ((const float4*)gamma)[threadIdx.x];
    float4 bv = ((const float4*)beta )[threadIdx.x];
    float4 o;
    o.x = dx * rstd * gv.x + bv.x;
    o.y = dy * rstd * gv.y + bv.y;
    o.z = dz * rstd * gv.z + bv.z;
    o.w = dw * rstd * gv.w + bv.w;
    ((float4*)(out + row * DIN))[threadIdx.x] = o;
}

// ---------------- generic NT SGEMM: C[M,N] = A[M,K] * B[N,K]^T + epilogue ---
// EPI: 0 = none, 1 = bias+ReLU, 2 = bias+softplus, 3 = +residual
template <int EPI>
__global__ __launch_bounds__(256)
void gemm_nt(const float* __restrict__ A, const float* __restrict__ B,
             const float* __restrict__ bias, const float* __restrict__ res,
             float* __restrict__ C, int M, int N, int K) {
    const int BM = 128, BN = 128, BK = 8, TM = 8, TN = 8;
    __shared__ float As[BK][BM];
    __shared__ float Bs[BK][BN];

    int tid  = threadIdx.x;
    int cRow = blockIdx.y * BM;
    int cCol = blockIdx.x * BN;
    int tCol = tid & 15;     // 0..15
    int tRow = tid >> 4;     // 0..15

    int aRow  = tid >> 1;          // 0..127
    int aCol4 = (tid & 1) * 4;     // 0 or 4

    float acc[TM][TN];
    #pragma unroll
    for (int i = 0; i < TM; i++)
        #pragma unroll
        for (int j = 0; j < TN; j++) acc[i][j] = 0.f;

    for (int k0 = 0; k0 < K; k0 += BK) {
        float4 a4 = *(const float4*)&A[(size_t)(cRow + aRow) * K + k0 + aCol4];
        float4 b4 = make_float4(0.f, 0.f, 0.f, 0.f);
        int bRow = cCol + aRow;
        if (bRow < N) b4 = *(const float4*)&B[(size_t)bRow * K + k0 + aCol4];
        As[aCol4 + 0][aRow] = a4.x;
        As[aCol4 + 1][aRow] = a4.y;
        As[aCol4 + 2][aRow] = a4.z;
        As[aCol4 + 3][aRow] = a4.w;
        Bs[aCol4 + 0][aRow] = b4.x;
        Bs[aCol4 + 1][aRow] = b4.y;
        Bs[aCol4 + 2][aRow] = b4.z;
        Bs[aCol4 + 3][aRow] = b4.w;
        __syncthreads();

        #pragma unroll
        for (int k = 0; k < BK; k++) {
            float rA[TM], rB[TN];
            #pragma unroll
            for (int i = 0; i < TM; i++) rA[i] = As[k][tRow * TM + i];
            #pragma unroll
            for (int j = 0; j < TN; j++) rB[j] = Bs[k][tCol * TN + j];
            #pragma unroll
            for (int i = 0; i < TM; i++)
                #pragma unroll
                for (int j = 0; j < TN; j++)
                    acc[i][j] = fmaf(rA[i], rB[j], acc[i][j]);
        }
        __syncthreads();
    }

    #pragma unroll
    for (int i = 0; i < TM; i++) {
        int row = cRow + tRow * TM + i;
        #pragma unroll
        for (int j = 0; j < TN; j++) {
            int col = cCol + tCol * TN + j;
            if (col < N) {
                float v = acc[i][j];
                if (EPI == 1) v = fmaxf(v + bias[col], 0.f);
                if (EPI == 2) v = softplusf(v + bias[col]);
                if (EPI == 3) v += res[(size_t)row * N + col];
                C[(size_t)row * N + col] = v;
            }
        }
    }
}

// ---------------- depthwise conv (k=3, pad=1) over seq + SiLU ---------------
__global__ void conv_silu_kernel(const float* __restrict__ hin,
                                 const float* __restrict__ w,
                                 float* __restrict__ out) {
    size_t t = (size_t)blockIdx.x * blockDim.x + threadIdx.x;
    if (t >= (size_t)MM * HH) return;
    int h = (int)(t & (HH - 1));
    size_t bl = t >> 10;               // row index (b*L + l)
    int l = (int)(bl & (LL - 1));
    float w0 = w[h * 3 + 0], w1 = w[h * 3 + 1], w2 = w[h * 3 + 2];
    float left  = (l > 0)      ? hin[t - HH] : 0.f;
    float mid   = hin[t];
    float right = (l < LL - 1) ? hin[t + HH] : 0.f;
    float v = w0 * left + w1 * mid + w2 * right;
    out[t] = v / (1.f + expf(-v));     // SiLU
}

// ---------------- selective scan: thread per (b, h, n) ----------------------
__global__ void scan_kernel(const float* __restrict__ xin,   // conv output
                            const float* __restrict__ dt,
                            const float* __restrict__ Aw,
                            const float* __restrict__ Dw,
                            float* __restrict__ y) {
    int t = blockIdx.x * blockDim.x + threadIdx.x;  // < B*H*NS = 131072
    int n  = t & (NS - 1);
    int hb = t >> 4;              // b*H + h
    int h  = hb & (HH - 1);
    int b  = hb >> 10;

    float a    = Aw[h * NS + n];
    float aneg = -expf(a);
    float inva = (fabsf(aneg) < 1e-5f) ? 1.f : 1.f / aneg;
    float d    = Dw[h];

    const float* xp = xin + (size_t)b * LL * HH + h;
    const float* dp = dt  + (size_t)b * LL * HH + h;
    float*       yp = y   + (size_t)b * LL * HH + h;

    float state = 0.f;
    for (int l = 0; l < LL; l++) {
        size_t off = (size_t)l * HH;
        float xt  = xp[off];
        float dtt = dp[off];
        float e   = __expf(aneg * dtt);
        float db  = (e - 1.f) * inva * dtt;
        state = fmaf(e, state, db * xt);
        float p = state * a;
        p += __shfl_xor_sync(0xffffffffu, p, 8);
        p += __shfl_xor_sync(0xffffffffu, p, 4);
        p += __shfl_xor_sync(0xffffffffu, p, 2);
        p += __shfl_xor_sync(0xffffffffu, p, 1);
        if (n == 0) yp[off] = fmaf(d, xt, p);
    }
}

// ---------------- launch ----------------------------------------------------
extern "C" void kernel_launch(void* const* d_in, const int* in_sizes, int n_in,
                              void* d_out, int out_size) {
    const float* x      = (const float*)d_in[0];
    const float* ln_g   = (const float*)d_in[1];
    const float* ln_b   = (const float*)d_in[2];
    const float* W_in   = (const float*)d_in[3];
    const float* conv_w = (const float*)d_in[4];
    const float* A      = (const float*)d_in[5];
    const float* D      = (const float*)d_in[6];
    const float* dt_W1  = (const float*)d_in[7];
    const float* dt_b1  = (const float*)d_in[8];
    const float* dt_W2  = (const float*)d_in[9];
    const float* dt_b2  = (const float*)d_in[10];
    const float* W_out  = (const float*)d_in[11];
    float* out = (float*)d_out;

    float *p_xn, *p_h, *p_hc, *p_dtr, *p_dt, *p_y;
    cudaGetSymbolAddress((void**)&p_xn,  g_xn);
    cudaGetSymbolAddress((void**)&p_h,   g_h);
    cudaGetSymbolAddress((void**)&p_hc,  g_hc);
    cudaGetSymbolAddress((void**)&p_dtr, g_dtr);
    cudaGetSymbolAddress((void**)&p_dt,  g_dt);
    cudaGetSymbolAddress((void**)&p_y,   g_y);

    // 1) LayerNorm
    ln_kernel<<<MM, 128>>>(x, ln_g, ln_b, p_xn);

    // 2) in_proj: h = xn @ W_in^T   [16384,512]x[1024,512]^T
    gemm_nt<0><<<dim3(HH / 128, MM / 128), 256>>>(p_xn, W_in, nullptr, nullptr,
                                                  p_h, MM, HH, DIN);

    // 3) depthwise conv + SiLU
    conv_silu_kernel<<<(MM * HH) / 256, 256>>>(p_h, conv_w, p_hc);

    // 4) dt hidden: relu(hc @ dt_W1^T + b1)   N=64
    gemm_nt<1><<<dim3(1, MM / 128), 256>>>(p_hc, dt_W1, dt_b1, nullptr,
                                           p_dtr, MM, RR, HH);

    // 5) dt: softplus(dtr @ dt_W2^T + b2)
    gemm_nt<2><<<dim3(HH / 128, MM / 128), 256>>>(p_dtr, dt_W2, dt_b2, nullptr,
                                                  p_dt, MM, HH, RR);

    // 6) selective scan
    scan_kernel<<<(BB * HH * NS) / 256, 256>>>(p_hc, p_dt, A, D, p_y);

    // 7) out proj + residual: out = y @ W_out^T + x
    gemm_nt<3><<<dim3(DIN / 128, MM / 128), 256>>>(p_y, W_out, nullptr, x,
                                                   out, MM, DIN, HH);
}

// round 4
// speedup vs baseline: 2.5056x; 2.5056x over previous
#include <cuda_runtime.h>
#include <cuda_bf16.h>
#include <cstdint>
#include <math.h>

// Problem dims (fixed by reference)
#define BB 8
#define LL 2048
#define DIN 512
#define HH 1024
#define NS 16
#define RR 64
#define MM (BB * LL)   // 16384

typedef __nv_bfloat16 bf16;

// ---------------- scratch (device globals; no allocation allowed) ----------
__device__ bf16  g_xn16 [(size_t)MM * DIN];   // layernorm output (bf16)
__device__ bf16  g_h16  [(size_t)MM * HH];    // in_proj output
__device__ bf16  g_hc16 [(size_t)MM * HH];    // conv+silu output
__device__ bf16  g_dtr16[(size_t)MM * RR];    // dt hidden
__device__ bf16  g_dt16 [(size_t)MM * HH];    // dt (softplus)
__device__ bf16  g_y16  [(size_t)MM * HH];    // scan output
__device__ bf16  g_win16 [(size_t)HH * DIN];
__device__ bf16  g_w1_16 [(size_t)RR * HH];
__device__ bf16  g_w2_16 [(size_t)HH * RR];
__device__ bf16  g_wout16[(size_t)DIN * HH];

// ---------------- helpers ---------------------------------------------------
__device__ __forceinline__ float blockReduce128(float v, float* sh) {
    #pragma unroll
    for (int o = 16; o > 0; o >>= 1) v += __shfl_xor_sync(0xffffffffu, v, o);
    int w = threadIdx.x >> 5;
    if ((threadIdx.x & 31) == 0) sh[w] = v;
    __syncthreads();
    float r = sh[0] + sh[1] + sh[2] + sh[3];
    __syncthreads();
    return r;
}

__device__ __forceinline__ float softplusf(float v) {
    return (v > 20.f) ? v : log1pf(expf(v));
}

// ---------------- f32 -> bf16 weight conversion -----------------------------
__global__ void f2bf_kernel(const float* __restrict__ in, bf16* __restrict__ out, int n) {
    int i = blockIdx.x * blockDim.x + threadIdx.x;
    if (i < n) out[i] = __float2bfloat16(in[i]);
}

// ---------------- LayerNorm: one block (128 thr) per row of 512 -------------
__global__ void ln_kernel(const float* __restrict__ x,
                          const float* __restrict__ gamma,
                          const float* __restrict__ beta,
                          bf16* __restrict__ out) {
    __shared__ float sh[4];
    size_t row = blockIdx.x;
    const float4* xr = (const float4*)(x + row * DIN);
    float4 v = xr[threadIdx.x];
    float s = blockReduce128(v.x + v.y + v.z + v.w, sh);
    float mu = s * (1.f / DIN);
    float dx = v.x - mu, dy = v.y - mu, dz = v.z - mu, dw = v.w - mu;
    float s2 = blockReduce128(dx*dx + dy*dy + dz*dz + dw*dw, sh);
    float rstd = rsqrtf(s2 * (1.f / DIN) + 1e-5f);
    float4 gv = ((const float4*)gamma)[threadIdx.x];
    float4 bv = ((const float4*)beta )[threadIdx.x];
    __nv_bfloat162* orow = (__nv_bfloat162*)(out + row * DIN);
    orow[2*threadIdx.x + 0] = __floats2bfloat162_rn(dx * rstd * gv.x + bv.x,
                                                    dy * rstd * gv.y + bv.y);
    orow[2*threadIdx.x + 1] = __floats2bfloat162_rn(dz * rstd * gv.z + bv.z,
                                                    dw * rstd * gv.w + bv.w);
}

// ---------------- MMA primitives --------------------------------------------
__device__ __forceinline__ void ldsm_x4(uint32_t& r0, uint32_t& r1,
                                        uint32_t& r2, uint32_t& r3,
                                        uint32_t addr) {
    asm volatile("ldmatrix.sync.aligned.m8n8.x4.shared.b16 {%0,%1,%2,%3}, [%4];"
                 : "=r"(r0), "=r"(r1), "=r"(r2), "=r"(r3) : "r"(addr));
}

__device__ __forceinline__ void mma_bf16(float* c4, const uint32_t* af,
                                         uint32_t b0, uint32_t b1) {
    asm volatile(
        "mma.sync.aligned.m16n8k16.row.col.f32.bf16.bf16.f32 "
        "{%0,%1,%2,%3}, {%4,%5,%6,%7}, {%8,%9}, {%0,%1,%2,%3};"
        : "+f"(c4[0]), "+f"(c4[1]), "+f"(c4[2]), "+f"(c4[3])
        : "r"(af[0]), "r"(af[1]), "r"(af[2]), "r"(af[3]), "r"(b0), "r"(b1));
}

// ---------------- bf16 tensor-core GEMM: C[M,N] = A[M,K] * B[N,K]^T ---------
// EPI: 0 = none (bf16 out), 1 = bias+ReLU (bf16), 2 = bias+softplus (bf16),
//      3 = +residual (f32 out)
template <int EPI, typename OutT>
__global__ __launch_bounds__(256)
void gemm_bf16(const bf16* __restrict__ A, const bf16* __restrict__ B,
               const float* __restrict__ bias, const float* __restrict__ res,
               OutT* __restrict__ C, int M, int N, int K) {
    // 128x128 block tile, BK=32. 8 warps in 2x4 grid, 64x32 warp tiles.
    __shared__ bf16 As[128 * 40];   // [row][40] padded (80B stride)
    __shared__ bf16 Bs[128 * 40];

    const int tid  = threadIdx.x;
    const int lane = tid & 31;
    const int wid  = tid >> 5;
    const int wRow = wid >> 2;      // 0..1  (64-row slab)
    const int wCol = wid & 3;       // 0..3  (32-col slab)
    const int bM = blockIdx.y * 128;
    const int bN = blockIdx.x * 128;

    const uint32_t sA = (uint32_t)__cvta_generic_to_shared(As);
    const uint32_t sB = (uint32_t)__cvta_generic_to_shared(Bs);

    // ldmatrix lane base addresses (byte offsets; +kk*2 per k-step)
    uint32_t aAddr[4], bAddr[2];
    {
        const int ar = lane & 15, ak = (lane >> 4) * 8;
        #pragma unroll
        for (int mi = 0; mi < 4; mi++)
            aAddr[mi] = sA + (uint32_t)(((wRow*64 + mi*16 + ar) * 40 + ak) * 2);
        const int br = ((lane >> 4) << 3) + (lane & 7);
        const int bk = ((lane >> 3) & 1) * 8;
        #pragma unroll
        for (int p = 0; p < 2; p++)
            bAddr[p] = sB + (uint32_t)(((wCol*32 + p*16 + br) * 40 + bk) * 2);
    }

    float acc[4][4][4];
    #pragma unroll
    for (int i = 0; i < 4; i++)
        #pragma unroll
        for (int j = 0; j < 4; j++)
            #pragma unroll
            for (int q = 0; q < 4; q++) acc[i][j][q] = 0.f;

    for (int k0 = 0; k0 < K; k0 += 32) {
        // stage tiles: 128 rows x 32 halves = 512 uint4, 2 per thread
        #pragma unroll
        for (int s = 0; s < 2; s++) {
            int idx = tid + s * 256;
            int r = idx >> 2;
            int c = (idx & 3) * 8;
            *(uint4*)&As[r * 40 + c] =
                *(const uint4*)&A[(size_t)(bM + r) * K + k0 + c];
            uint4 bv = make_uint4(0u, 0u, 0u, 0u);
            int brow = bN + r;
            if (brow < N) bv = *(const uint4*)&B[(size_t)brow * K + k0 + c];
            *(uint4*)&Bs[r * 40 + c] = bv;
        }
        __syncthreads();

        #pragma unroll
        for (int kk = 0; kk < 32; kk += 16) {
            uint32_t fa[4][4], fb[2][4];
            #pragma unroll
            for (int mi = 0; mi < 4; mi++)
                ldsm_x4(fa[mi][0], fa[mi][1], fa[mi][2], fa[mi][3],
                        aAddr[mi] + kk * 2);
            #pragma unroll
            for (int p = 0; p < 2; p++)
                ldsm_x4(fb[p][0], fb[p][1], fb[p][2], fb[p][3],
                        bAddr[p] + kk * 2);
            #pragma unroll
            for (int mi = 0; mi < 4; mi++)
                #pragma unroll
                for (int p = 0; p < 2; p++)
                    #pragma unroll
                    for (int q = 0; q < 2; q++)
                        mma_bf16(acc[mi][p*2 + q], fa[mi],
                                 fb[p][2*q], fb[p][2*q + 1]);
        }
        __syncthreads();
    }

    // epilogue
    const int g = lane >> 2, tq = lane & 3;
    #pragma unroll
    for (int mi = 0; mi < 4; mi++) {
        #pragma unroll
        for (int ni = 0; ni < 4; ni++) {
            int row = bM + wRow*64 + mi*16 + g;
            int col = bN + wCol*32 + ni*8 + tq*2;
            if (col >= N) continue;
            float v0 = acc[mi][ni][0], v1 = acc[mi][ni][1];
            float v2 = acc[mi][ni][2], v3 = acc[mi][ni][3];
            if (EPI == 1) {
                float b0 = bias[col], b1 = bias[col+1];
                v0 = fmaxf(v0 + b0, 0.f); v1 = fmaxf(v1 + b1, 0.f);
                v2 = fmaxf(v2 + b0, 0.f); v3 = fmaxf(v3 + b1, 0.f);
            }
            if (EPI == 2) {
                float b0 = bias[col], b1 = bias[col+1];
                v0 = softplusf(v0 + b0); v1 = softplusf(v1 + b1);
                v2 = softplusf(v2 + b0); v3 = softplusf(v3 + b1);
            }
            if (EPI == 3) {
                const float2 r0 = *(const float2*)&res[(size_t)row * N + col];
                const float2 r1 = *(const float2*)&res[(size_t)(row+8) * N + col];
                v0 += r0.x; v1 += r0.y; v2 += r1.x; v3 += r1.y;
            }
            if (sizeof(OutT) == 4) {   // f32 out
                float2* o0 = (float2*)((float*)C + (size_t)row * N + col);
                float2* o1 = (float2*)((float*)C + (size_t)(row+8) * N + col);
                *o0 = make_float2(v0, v1);
                *o1 = make_float2(v2, v3);
            } else {                   // bf16 out
                *(__nv_bfloat162*)((bf16*)C + (size_t)row * N + col) =
                    __floats2bfloat162_rn(v0, v1);
                *(__nv_bfloat162*)((bf16*)C + (size_t)(row+8) * N + col) =
                    __floats2bfloat162_rn(v2, v3);
            }
        }
    }
}

// ---------------- depthwise conv (k=3, pad=1) over seq + SiLU ---------------
__global__ void conv_silu_kernel(const bf16* __restrict__ hin,
                                 const float* __restrict__ w,
                                 bf16* __restrict__ out) {
    size_t t = (size_t)blockIdx.x * blockDim.x + threadIdx.x;
    if (t >= (size_t)MM * HH) return;
    int h = (int)(t & (HH - 1));
    size_t bl = t >> 10;
    int l = (int)(bl & (LL - 1));
    float w0 = w[h * 3 + 0], w1 = w[h * 3 + 1], w2 = w[h * 3 + 2];
    float left  = (l > 0)      ? __bfloat162float(hin[t - HH]) : 0.f;
    float mid   = __bfloat162float(hin[t]);
    float right = (l < LL - 1) ? __bfloat162float(hin[t + HH]) : 0.f;
    float v = w0 * left + w1 * mid + w2 * right;
    out[t] = __float2bfloat16(v / (1.f + expf(-v)));
}

// ---------------- selective scan: thread per (b, h, n) ----------------------
__global__ void scan_kernel(const bf16* __restrict__ xin,
                            const bf16* __restrict__ dt,
                            const float* __restrict__ Aw,
                            const float* __restrict__ Dw,
                            bf16* __restrict__ y) {
    int t = blockIdx.x * blockDim.x + threadIdx.x;  // < B*H*NS = 131072
    int n  = t & (NS - 1);
    int hb = t >> 4;
    int h  = hb & (HH - 1);
    int b  = hb >> 10;

    float a    = Aw[h * NS + n];
    float aneg = -expf(a);
    float inva = (fabsf(aneg) < 1e-5f) ? 1.f : 1.f / aneg;
    float d    = Dw[h];

    const bf16* xp = xin + (size_t)b * LL * HH + h;
    const bf16* dp = dt  + (size_t)b * LL * HH + h;
    bf16*       yp = y   + (size_t)b * LL * HH + h;

    float state = 0.f;
    for (int l = 0; l < LL; l++) {
        size_t off = (size_t)l * HH;
        float xt  = __bfloat162float(xp[off]);
        float dtt = __bfloat162float(dp[off]);
        float e   = __expf(aneg * dtt);
        float db  = (e - 1.f) * inva * dtt;
        state = fmaf(e, state, db * xt);
        float p = state * a;
        p += __shfl_xor_sync(0xffffffffu, p, 8);
        p += __shfl_xor_sync(0xffffffffu, p, 4);
        p += __shfl_xor_sync(0xffffffffu, p, 2);
        p += __shfl_xor_sync(0xffffffffu, p, 1);
        if (n == 0) yp[off] = __float2bfloat16(fmaf(d, xt, p));
    }
}

// ---------------- launch ----------------------------------------------------
extern "C" void kernel_launch(void* const* d_in, const int* in_sizes, int n_in,
                              void* d_out, int out_size) {
    const float* x      = (const float*)d_in[0];
    const float* ln_g   = (const float*)d_in[1];
    const float* ln_b   = (const float*)d_in[2];
    const float* W_in   = (const float*)d_in[3];
    const float* conv_w = (const float*)d_in[4];
    const float* A      = (const float*)d_in[5];
    const float* D      = (const float*)d_in[6];
    const float* dt_W1  = (const float*)d_in[7];
    const float* dt_b1  = (const float*)d_in[8];
    const float* dt_W2  = (const float*)d_in[9];
    const float* dt_b2  = (const float*)d_in[10];
    const float* W_out  = (const float*)d_in[11];
    float* out = (float*)d_out;

    bf16 *p_xn, *p_h, *p_hc, *p_dtr, *p_dt, *p_y;
    bf16 *p_win, *p_w1, *p_w2, *p_wout;
    cudaGetSymbolAddress((void**)&p_xn,  g_xn16);
    cudaGetSymbolAddress((void**)&p_h,   g_h16);
    cudaGetSymbolAddress((void**)&p_hc,  g_hc16);
    cudaGetSymbolAddress((void**)&p_dtr, g_dtr16);
    cudaGetSymbolAddress((void**)&p_dt,  g_dt16);
    cudaGetSymbolAddress((void**)&p_y,   g_y16);
    cudaGetSymbolAddress((void**)&p_win, g_win16);
    cudaGetSymbolAddress((void**)&p_w1,  g_w1_16);
    cudaGetSymbolAddress((void**)&p_w2,  g_w2_16);
    cudaGetSymbolAddress((void**)&p_wout,g_wout16);

    // 0) weight conversion f32 -> bf16
    f2bf_kernel<<<(HH*DIN + 255)/256, 256>>>(W_in,  p_win,  HH*DIN);
    f2bf_kernel<<<(RR*HH  + 255)/256, 256>>>(dt_W1, p_w1,   RR*HH);
    f2bf_kernel<<<(HH*RR  + 255)/256, 256>>>(dt_W2, p_w2,   HH*RR);
    f2bf_kernel<<<(DIN*HH + 255)/256, 256>>>(W_out, p_wout, DIN*HH);

    // 1) LayerNorm (f32 in, bf16 out)
    ln_kernel<<<MM, 128>>>(x, ln_g, ln_b, p_xn);

    // 2) in_proj: h = xn @ W_in^T   [16384,512] x [1024,512]^T
    gemm_bf16<0, bf16><<<dim3(HH/128, MM/128), 256>>>(
        p_xn, p_win, nullptr, nullptr, p_h, MM, HH, DIN);

    // 3) depthwise conv + SiLU
    conv_silu_kernel<<<(MM * HH) / 256, 256>>>(p_h, conv_w, p_hc);

    // 4) dt hidden: relu(hc @ dt_W1^T + b1)   N=64
    gemm_bf16<1, bf16><<<dim3(1, MM/128), 256>>>(
        p_hc, p_w1, dt_b1, nullptr, p_dtr, MM, RR, HH);

    // 5) dt: softplus(dtr @ dt_W2^T + b2)
    gemm_bf16<2, bf16><<<dim3(HH/128, MM/128), 256>>>(
        p_dtr, p_w2, dt_b2, nullptr, p_dt, MM, HH, RR);

    // 6) selective scan
    scan_kernel<<<(BB * HH * NS) / 256, 256>>>(p_hc, p_dt, A, D, p_y);

    // 7) out proj + residual: out = y @ W_out^T + x
    gemm_bf16<3, float><<<dim3(DIN/128, MM/128), 256>>>(
        p_y, p_wout, nullptr, x, out, MM, DIN, HH);
}